// round 1
// baseline (speedup 1.0000x reference)
#include <cuda_runtime.h>
#include <cuda_bf16.h>
#include <cstdint>

// WMAE: sum_{i,j} w[j%3] * |t1 - t2| / n_sample
// w = {300, 1, 200}
//
// Two-pass deterministic reduction:
//   pass 1: grid-stride float4, per-block partial sums -> __device__ scratch
//   pass 2: single block reduces partials in double, divides by n_sample

#define NBLOCKS 1024
#define NTHREADS 256

__device__ float g_partials[NBLOCKS];

// pattern[v % 3] = weights for float4 #v (element indices 4v..4v+3)
// 4 ≡ 1 (mod 3) so pattern cycles with v%3.
// v%3==0: idx%3 = 0,1,2,0 -> 300,1,200,300
// v%3==1: idx%3 = 1,2,0,1 -> 1,200,300,1
// v%3==2: idx%3 = 2,0,1,2 -> 200,300,1,200
__constant__ float4 c_pat[3] = {
    {300.0f, 1.0f, 200.0f, 300.0f},
    {1.0f, 200.0f, 300.0f, 1.0f},
    {200.0f, 300.0f, 1.0f, 200.0f}
};
__constant__ float c_w[3] = {300.0f, 1.0f, 200.0f};

__global__ __launch_bounds__(NTHREADS) void wmae_partial_kernel(
    const float* __restrict__ t1,
    const float* __restrict__ t2,
    long long n)  // total element count
{
    long long n4 = n >> 2;  // number of float4's
    const float4* __restrict__ a4 = reinterpret_cast<const float4*>(t1);
    const float4* __restrict__ b4 = reinterpret_cast<const float4*>(t2);

    float acc = 0.0f;
    long long stride = (long long)gridDim.x * blockDim.x;
    long long tid0 = (long long)blockIdx.x * blockDim.x + threadIdx.x;

    for (long long v = tid0; v < n4; v += stride) {
        float4 a = __ldcs(&a4[v]);
        float4 b = __ldcs(&b4[v]);
        float4 w = c_pat[(int)(v % 3)];
        acc = fmaf(w.x, fabsf(a.x - b.x), acc);
        acc = fmaf(w.y, fabsf(a.y - b.y), acc);
        acc = fmaf(w.z, fabsf(a.z - b.z), acc);
        acc = fmaf(w.w, fabsf(a.w - b.w), acc);
    }

    // scalar tail (n % 4 != 0), handled by thread 0 of block 0
    if (blockIdx.x == 0 && threadIdx.x == 0) {
        for (long long i = n4 << 2; i < n; i++) {
            float d = fabsf(t1[i] - t2[i]);
            acc = fmaf(c_w[(int)(i % 3)], d, acc);
        }
    }

    // block reduction
    __shared__ float sdata[NTHREADS / 32];
    // warp reduce
    #pragma unroll
    for (int off = 16; off > 0; off >>= 1)
        acc += __shfl_xor_sync(0xFFFFFFFFu, acc, off);
    int lane = threadIdx.x & 31;
    int wid = threadIdx.x >> 5;
    if (lane == 0) sdata[wid] = acc;
    __syncthreads();
    if (wid == 0) {
        float v = (lane < NTHREADS / 32) ? sdata[lane] : 0.0f;
        #pragma unroll
        for (int off = (NTHREADS / 64); off > 0; off >>= 1)
            v += __shfl_xor_sync(0xFFFFFFFFu, v, off);
        if (lane == 0) g_partials[blockIdx.x] = v;
    }
}

__global__ __launch_bounds__(1024) void wmae_final_kernel(
    float* __restrict__ out, long long n_sample)
{
    int tid = threadIdx.x;
    double acc = 0.0;
    for (int i = tid; i < NBLOCKS; i += 1024)
        acc += (double)g_partials[i];

    __shared__ double sdata[32];
    #pragma unroll
    for (int off = 16; off > 0; off >>= 1)
        acc += __shfl_xor_sync(0xFFFFFFFFu, acc, off);
    int lane = tid & 31;
    int wid = tid >> 5;
    if (lane == 0) sdata[wid] = acc;
    __syncthreads();
    if (wid == 0) {
        double v = (lane < 32) ? sdata[lane] : 0.0;
        #pragma unroll
        for (int off = 16; off > 0; off >>= 1)
            v += __shfl_xor_sync(0xFFFFFFFFu, v, off);
        if (lane == 0) out[0] = (float)(v / (double)n_sample);
    }
}

extern "C" void kernel_launch(void* const* d_in, const int* in_sizes, int n_in,
                              void* d_out, int out_size) {
    const float* t1 = (const float*)d_in[0];
    const float* t2 = (const float*)d_in[1];
    float* out = (float*)d_out;
    long long n = (long long)in_sizes[0];       // total elements (n_sample * 3)
    long long n_sample = n / 3;

    wmae_partial_kernel<<<NBLOCKS, NTHREADS>>>(t1, t2, n);
    wmae_final_kernel<<<1, 1024>>>(out, n_sample);
}

// round 2
// speedup vs baseline: 1.4117x; 1.4117x over previous
#include <cuda_runtime.h>
#include <cuda_bf16.h>
#include <cstdint>

// WMAE: sum_{i,j} w[j%3] * |t1[i,j] - t2[i,j]| / n_sample, w = {300, 1, 200}
//
// Single-kernel deterministic reduction:
//   - grid-stride float4 streaming loads, per-thread fp32 accum
//   - per-block partial -> __device__ scratch
//   - last-block-done pattern: final block reduces all partials in double
//     (fixed order -> deterministic), writes out, resets counter for graph replay

#define NBLOCKS 1024
#define NTHREADS 256

__device__ float g_partials[NBLOCKS];
__device__ unsigned int g_done_count;  // zero-initialized; reset by last block

// pattern[v % 3] = weights for float4 #v (element indices 4v..4v+3); 4 ≡ 1 (mod 3)
__constant__ float4 c_pat[3] = {
    {300.0f, 1.0f, 200.0f, 300.0f},
    {1.0f, 200.0f, 300.0f, 1.0f},
    {200.0f, 300.0f, 1.0f, 200.0f}
};
__constant__ float c_w[3] = {300.0f, 1.0f, 200.0f};

__global__ __launch_bounds__(NTHREADS) void wmae_fused_kernel(
    const float* __restrict__ t1,
    const float* __restrict__ t2,
    float* __restrict__ out,
    int n,          // total element count (fits in int: 12.58M)
    float inv_n_sample_num)  // unused placeholder (kept 0 args minimal)
{
    const int n4 = n >> 2;
    const float4* __restrict__ a4 = reinterpret_cast<const float4*>(t1);
    const float4* __restrict__ b4 = reinterpret_cast<const float4*>(t2);

    const int stride = gridDim.x * blockDim.x;      // 262144, ≡ 1 (mod 3)
    const int tid0 = blockIdx.x * blockDim.x + threadIdx.x;

    float acc = 0.0f;
    int p = tid0 % 3;  // pattern index; advances by stride%3 == 1 per iteration
    for (int v = tid0; v < n4; v += stride) {
        float4 a = __ldcs(&a4[v]);
        float4 b = __ldcs(&b4[v]);
        float4 w = c_pat[p];
        acc = fmaf(w.x, fabsf(a.x - b.x), acc);
        acc = fmaf(w.y, fabsf(a.y - b.y), acc);
        acc = fmaf(w.z, fabsf(a.z - b.z), acc);
        acc = fmaf(w.w, fabsf(a.w - b.w), acc);
        p = (p == 2) ? 0 : p + 1;
    }

    // scalar tail (n % 4 != 0)
    if (blockIdx.x == 0 && threadIdx.x == 0) {
        for (int i = n4 << 2; i < n; i++) {
            acc = fmaf(c_w[i % 3], fabsf(t1[i] - t2[i]), acc);
        }
    }

    // block reduction (fp32)
    __shared__ float sdata[NTHREADS / 32];
    #pragma unroll
    for (int off = 16; off > 0; off >>= 1)
        acc += __shfl_xor_sync(0xFFFFFFFFu, acc, off);
    const int lane = threadIdx.x & 31;
    const int wid = threadIdx.x >> 5;
    if (lane == 0) sdata[wid] = acc;
    __syncthreads();

    __shared__ bool s_is_last;
    if (threadIdx.x == 0) {
        float v = sdata[0];
        #pragma unroll
        for (int w = 1; w < NTHREADS / 32; w++) v += sdata[w];
        g_partials[blockIdx.x] = v;
        __threadfence();
        unsigned int prev = atomicAdd(&g_done_count, 1u);
        s_is_last = (prev == (unsigned int)(gridDim.x - 1));
    }
    __syncthreads();

    if (!s_is_last) return;

    // ---- last block: deterministic final reduce in double ----
    double dacc = 0.0;
    for (int i = threadIdx.x; i < NBLOCKS; i += NTHREADS)
        dacc += (double)g_partials[i];

    __shared__ double ddata[NTHREADS / 32];
    #pragma unroll
    for (int off = 16; off > 0; off >>= 1)
        dacc += __shfl_xor_sync(0xFFFFFFFFu, dacc, off);
    if (lane == 0) ddata[wid] = dacc;
    __syncthreads();
    if (threadIdx.x == 0) {
        double v = ddata[0];
        #pragma unroll
        for (int w = 1; w < NTHREADS / 32; w++) v += ddata[w];
        long long n_sample = (long long)(n / 3);
        out[0] = (float)(v / (double)n_sample);
        g_done_count = 0;  // reset for next graph replay
    }
}

extern "C" void kernel_launch(void* const* d_in, const int* in_sizes, int n_in,
                              void* d_out, int out_size) {
    const float* t1 = (const float*)d_in[0];
    const float* t2 = (const float*)d_in[1];
    float* out = (float*)d_out;
    int n = in_sizes[0];  // total elements (n_sample * 3)

    wmae_fused_kernel<<<NBLOCKS, NTHREADS>>>(t1, t2, out, n, 0.0f);
}